// round 11
// baseline (speedup 1.0000x reference)
#include <cuda_runtime.h>

#define HH 50
#define TT 96
#define NPRED 12
#define NTH 64
#define EPB 4   // batch elements per block (per thread) — weights shared in registers

typedef unsigned long long u64;

__device__ __forceinline__ u64 pk2(float lo, float hi) {
    u64 r; asm("mov.b64 %0, {%1,%2};" : "=l"(r) : "f"(lo), "f"(hi)); return r;
}
__device__ __forceinline__ void upk2(u64 v, float &lo, float &hi) {
    asm("mov.b64 {%0,%1}, %2;" : "=f"(lo), "=f"(hi) : "l"(v));
}
__device__ __forceinline__ u64 ffma2(u64 a, u64 b, u64 c) {
    u64 d; asm("fma.rn.f32x2 %0, %1, %2, %3;" : "=l"(d) : "l"(a), "l"(b), "l"(c)); return d;
}
__device__ __forceinline__ float ftanh(float x) {
    float y; asm("tanh.approx.f32 %0, %1;" : "=f"(y) : "f"(x)); return y;
}
__device__ __forceinline__ float fsig(float x) {
    return fmaf(0.5f, ftanh(0.5f * x), 0.5f);
}

__global__ __launch_bounds__(NTH)
void lstm_recursive_kernel(const float* __restrict__ x,
                           const float* __restrict__ W_ih,
                           const float* __restrict__ W_hh,
                           const float* __restrict__ b_ih,
                           const float* __restrict__ b_hh,
                           const float* __restrict__ W_fc,
                           const float* __restrict__ b_fc,
                           float* __restrict__ out) {
    const int j  = threadIdx.x;                    // 0..63, ALL lanes active (branchless)
    const int jr = (j < HH) ? j : (HH - 1);        // clamped row: lanes 50-63 duplicate row 49
    const int b0 = blockIdx.x * EPB;

    // h buffers padded to 64: [0..49] real, [50..63] scratch written by clamped lanes
    __shared__ __align__(16) float sh[EPB][2][64];
    __shared__ float swin[EPB][TT + NPRED];
    __shared__ float sred[EPB][64];

#pragma unroll
    for (int e = 0; e < EPB; e++)
        for (int i = j; i < TT; i += NTH) swin[e][i] = x[(b0 + e) * TT + i];

    // thread owns gate rows jr, jr+50, jr+100, jr+150 (i,f,g,o) for ALL EPB elements
    u64 w[4][25];                    // 200 regs of packed W_hh K-pairs (shared across elements)
    float wih[4], bsum[4];
#pragma unroll
    for (int g = 0; g < 4; g++) {
        const int row = g * HH + jr;
        const float2* wr = (const float2*)(W_hh + row * HH);   // 8B aligned
#pragma unroll
        for (int k = 0; k < 25; k++) {
            float2 v = wr[k];
            w[g][k] = pk2(v.x, v.y);
        }
        wih[g]  = W_ih[row];
        bsum[g] = b_ih[row] + b_hh[row];
    }
    const float wfc = (j < HH) ? W_fc[jr] : 0.0f;   // zero so padded sred entries are 0
    const float bfc = b_fc[0];

    for (int p = 0; p < NPRED; p++) {
#pragma unroll
        for (int e = 0; e < EPB; e++) { sh[e][0][j] = 0.0f; sh[e][1][j] = 0.0f; }
        float c[EPB], hnew[EPB];
#pragma unroll
        for (int e = 0; e < EPB; e++) { c[e] = 0.0f; hnew[e] = 0.0f; }
        __syncthreads();

#pragma unroll 1
        for (int t = 0; t < TT; t++) {
            const int buf = t & 1;
            // 4 gate chains per element -> 16 independent FFMA2 chains
            u64 a[EPB][4];
#pragma unroll
            for (int e = 0; e < EPB; e++) {
                const float xt = swin[e][p + t];
                a[e][0] = pk2(fmaf(xt, wih[0], bsum[0]), 0.0f);
                a[e][1] = pk2(fmaf(xt, wih[1], bsum[1]), 0.0f);
                a[e][2] = pk2(fmaf(xt, wih[2], bsum[2]), 0.0f);
                a[e][3] = pk2(fmaf(xt, wih[3], bsum[3]), 0.0f);
            }
#pragma unroll
            for (int cc = 0; cc < 12; cc++) {
#pragma unroll
                for (int e = 0; e < EPB; e++) {
                    ulonglong2 hv = ((const ulonglong2*)sh[e][buf])[cc];  // LDS.128 bcast
                    a[e][0] = ffma2(w[0][2 * cc], hv.x, a[e][0]);
                    a[e][1] = ffma2(w[1][2 * cc], hv.x, a[e][1]);
                    a[e][2] = ffma2(w[2][2 * cc], hv.x, a[e][2]);
                    a[e][3] = ffma2(w[3][2 * cc], hv.x, a[e][3]);
                    a[e][0] = ffma2(w[0][2 * cc + 1], hv.y, a[e][0]);
                    a[e][1] = ffma2(w[1][2 * cc + 1], hv.y, a[e][1]);
                    a[e][2] = ffma2(w[2][2 * cc + 1], hv.y, a[e][2]);
                    a[e][3] = ffma2(w[3][2 * cc + 1], hv.y, a[e][3]);
                }
            }
#pragma unroll
            for (int e = 0; e < EPB; e++) {        // k = 48, 49
                u64 ht = ((const u64*)sh[e][buf])[24];
                a[e][0] = ffma2(w[0][24], ht, a[e][0]);
                a[e][1] = ffma2(w[1][24], ht, a[e][1]);
                a[e][2] = ffma2(w[2][24], ht, a[e][2]);
                a[e][3] = ffma2(w[3][24], ht, a[e][3]);
            }
#pragma unroll
            for (int e = 0; e < EPB; e++) {
                float l0, hi0, l1, hi1, l2, hi2, l3, hi3;
                upk2(a[e][0], l0, hi0);
                upk2(a[e][1], l1, hi1);
                upk2(a[e][2], l2, hi2);
                upk2(a[e][3], l3, hi3);
                const float i_ = fsig(l0 + hi0);
                const float f_ = fsig(l1 + hi1);
                const float g_ = ftanh(l2 + hi2);
                const float o_ = fsig(l3 + hi3);
                c[e]    = fmaf(f_, c[e], i_ * g_);
                hnew[e] = o_ * ftanh(c[e]);
                sh[e][buf ^ 1][j] = hnew[e];       // lanes 50-63 write pad slots (harmless)
            }
            __syncthreads();                       // new h visible for next step
        }

        // FC head: out = h . W_fc + b_fc  (wfc==0 for pad lanes -> sred pad entries are 0)
#pragma unroll
        for (int e = 0; e < EPB; e++) sred[e][j] = hnew[e] * wfc;
        __syncthreads();
        if (j < EPB) {
            float s = bfc;
#pragma unroll
            for (int k = 0; k < HH; k++) s += sred[j][k];
            swin[j][TT + p] = s;
            out[(b0 + j) * NPRED + p] = s;
        }
        __syncthreads();
    }
}

extern "C" void kernel_launch(void* const* d_in, const int* in_sizes, int n_in,
                              void* d_out, int out_size) {
    const float* x    = (const float*)d_in[0];
    const float* W_ih = (const float*)d_in[1];
    const float* W_hh = (const float*)d_in[2];
    const float* b_ih = (const float*)d_in[3];
    const float* b_hh = (const float*)d_in[4];
    const float* W_fc = (const float*)d_in[5];
    const float* b_fc = (const float*)d_in[6];
    float* out = (float*)d_out;

    const int B = out_size / NPRED;               // 1024
    lstm_recursive_kernel<<<B / EPB, NTH>>>(x, W_ih, W_hh, b_ih, b_hh, W_fc, b_fc, out);
}

// round 12
// speedup vs baseline: 1.1185x; 1.1185x over previous
#include <cuda_runtime.h>

#define HH 50
#define TT 96
#define NPRED 12
#define NTH 64
#define EPB 3   // batch elements per block (per thread) — weights shared in registers

typedef unsigned long long u64;

__device__ __forceinline__ u64 pk2(float lo, float hi) {
    u64 r; asm("mov.b64 %0, {%1,%2};" : "=l"(r) : "f"(lo), "f"(hi)); return r;
}
__device__ __forceinline__ void upk2(u64 v, float &lo, float &hi) {
    asm("mov.b64 {%0,%1}, %2;" : "=f"(lo), "=f"(hi) : "l"(v));
}
__device__ __forceinline__ u64 ffma2(u64 a, u64 b, u64 c) {
    u64 d; asm("fma.rn.f32x2 %0, %1, %2, %3;" : "=l"(d) : "l"(a), "l"(b), "l"(c)); return d;
}
__device__ __forceinline__ float ftanh(float x) {
    float y; asm("tanh.approx.f32 %0, %1;" : "=f"(y) : "f"(x)); return y;
}
__device__ __forceinline__ float fsig(float x) {
    return fmaf(0.5f, ftanh(0.5f * x), 0.5f);
}

__global__ __launch_bounds__(NTH)
void lstm_recursive_kernel(const float* __restrict__ x,
                           const float* __restrict__ W_ih,
                           const float* __restrict__ W_hh,
                           const float* __restrict__ b_ih,
                           const float* __restrict__ b_hh,
                           const float* __restrict__ W_fc,
                           const float* __restrict__ b_fc,
                           float* __restrict__ out, int B) {
    const int j  = threadIdx.x;                    // 0..63, ALL lanes active (branchless)
    const int jr = (j < HH) ? j : (HH - 1);        // clamped row: lanes 50-63 duplicate row 49
    const int b0 = blockIdx.x * EPB;

    // h buffers padded to 64: [0..49] real, [50..63] scratch written by clamped lanes
    __shared__ __align__(16) float sh[EPB][2][64];
    __shared__ float swin[EPB][TT + NPRED];
    __shared__ float sred[EPB][64];

#pragma unroll
    for (int e = 0; e < EPB; e++) {
        int src = b0 + e; if (src > B - 1) src = B - 1;   // clamp (duplicate work, guarded out)
        for (int i = j; i < TT; i += NTH) swin[e][i] = x[src * TT + i];
    }

    // thread owns gate rows jr, jr+50, jr+100, jr+150 (i,f,g,o) for ALL EPB elements
    u64 w[4][25];                    // 200 regs of packed W_hh K-pairs (shared across elements)
    float wih[4], bsum[4];
#pragma unroll
    for (int g = 0; g < 4; g++) {
        const int row = g * HH + jr;
        const float2* wr = (const float2*)(W_hh + row * HH);   // 8B aligned
#pragma unroll
        for (int k = 0; k < 25; k++) {
            float2 v = wr[k];
            w[g][k] = pk2(v.x, v.y);
        }
        wih[g]  = W_ih[row];
        bsum[g] = b_ih[row] + b_hh[row];
    }
    const float wfc = (j < HH) ? W_fc[jr] : 0.0f;   // zero so padded sred entries are 0
    const float bfc = b_fc[0];

    for (int p = 0; p < NPRED; p++) {
#pragma unroll
        for (int e = 0; e < EPB; e++) { sh[e][0][j] = 0.0f; sh[e][1][j] = 0.0f; }
        float c[EPB], hnew[EPB];
#pragma unroll
        for (int e = 0; e < EPB; e++) { c[e] = 0.0f; hnew[e] = 0.0f; }
        __syncthreads();

#pragma unroll 1
        for (int t = 0; t < TT; t++) {
            const int buf = t & 1;
            // 4 gate chains per element -> 12 independent FFMA2 chains
            u64 a[EPB][4];
#pragma unroll
            for (int e = 0; e < EPB; e++) {
                const float xt = swin[e][p + t];
                a[e][0] = pk2(fmaf(xt, wih[0], bsum[0]), 0.0f);
                a[e][1] = pk2(fmaf(xt, wih[1], bsum[1]), 0.0f);
                a[e][2] = pk2(fmaf(xt, wih[2], bsum[2]), 0.0f);
                a[e][3] = pk2(fmaf(xt, wih[3], bsum[3]), 0.0f);
            }
#pragma unroll
            for (int cc = 0; cc < 12; cc++) {
#pragma unroll
                for (int e = 0; e < EPB; e++) {
                    ulonglong2 hv = ((const ulonglong2*)sh[e][buf])[cc];  // LDS.128 bcast
                    a[e][0] = ffma2(w[0][2 * cc], hv.x, a[e][0]);
                    a[e][1] = ffma2(w[1][2 * cc], hv.x, a[e][1]);
                    a[e][2] = ffma2(w[2][2 * cc], hv.x, a[e][2]);
                    a[e][3] = ffma2(w[3][2 * cc], hv.x, a[e][3]);
                    a[e][0] = ffma2(w[0][2 * cc + 1], hv.y, a[e][0]);
                    a[e][1] = ffma2(w[1][2 * cc + 1], hv.y, a[e][1]);
                    a[e][2] = ffma2(w[2][2 * cc + 1], hv.y, a[e][2]);
                    a[e][3] = ffma2(w[3][2 * cc + 1], hv.y, a[e][3]);
                }
            }
#pragma unroll
            for (int e = 0; e < EPB; e++) {        // k = 48, 49
                u64 ht = ((const u64*)sh[e][buf])[24];
                a[e][0] = ffma2(w[0][24], ht, a[e][0]);
                a[e][1] = ffma2(w[1][24], ht, a[e][1]);
                a[e][2] = ffma2(w[2][24], ht, a[e][2]);
                a[e][3] = ffma2(w[3][24], ht, a[e][3]);
            }
#pragma unroll
            for (int e = 0; e < EPB; e++) {
                float l0, hi0, l1, hi1, l2, hi2, l3, hi3;
                upk2(a[e][0], l0, hi0);
                upk2(a[e][1], l1, hi1);
                upk2(a[e][2], l2, hi2);
                upk2(a[e][3], l3, hi3);
                const float i_ = fsig(l0 + hi0);
                const float f_ = fsig(l1 + hi1);
                const float g_ = ftanh(l2 + hi2);
                const float o_ = fsig(l3 + hi3);
                c[e]    = fmaf(f_, c[e], i_ * g_);
                hnew[e] = o_ * ftanh(c[e]);
                sh[e][buf ^ 1][j] = hnew[e];       // lanes 50-63 write pad slots (harmless)
            }
            __syncthreads();                       // new h visible for next step
        }

        // FC head: out = h . W_fc + b_fc  (wfc==0 for pad lanes -> sred pad entries are 0)
#pragma unroll
        for (int e = 0; e < EPB; e++) sred[e][j] = hnew[e] * wfc;
        __syncthreads();
        if (j < EPB) {
            float s = bfc;
#pragma unroll
            for (int k = 0; k < HH; k++) s += sred[j][k];
            swin[j][TT + p] = s;
            if (b0 + j < B) out[(b0 + j) * NPRED + p] = s;
        }
        __syncthreads();
    }
}

extern "C" void kernel_launch(void* const* d_in, const int* in_sizes, int n_in,
                              void* d_out, int out_size) {
    const float* x    = (const float*)d_in[0];
    const float* W_ih = (const float*)d_in[1];
    const float* W_hh = (const float*)d_in[2];
    const float* b_ih = (const float*)d_in[3];
    const float* b_hh = (const float*)d_in[4];
    const float* W_fc = (const float*)d_in[5];
    const float* b_fc = (const float*)d_in[6];
    float* out = (float*)d_out;

    const int B = out_size / NPRED;                 // 1024
    const int grid = (B + EPB - 1) / EPB;           // 342
    lstm_recursive_kernel<<<grid, NTH>>>(x, W_ih, W_hh, b_ih, b_hh, W_fc, b_fc, out, B);
}

// round 13
// speedup vs baseline: 1.6369x; 1.4635x over previous
#include <cuda_runtime.h>

#define HH 50
#define TT 96
#define NPRED 12
#define NTH 64
#define EPB 2   // batch elements per block (per thread) — weights shared in registers

typedef unsigned long long u64;

__device__ __forceinline__ u64 pk2(float lo, float hi) {
    u64 r; asm("mov.b64 %0, {%1,%2};" : "=l"(r) : "f"(lo), "f"(hi)); return r;
}
__device__ __forceinline__ void upk2(u64 v, float &lo, float &hi) {
    asm("mov.b64 {%0,%1}, %2;" : "=f"(lo), "=f"(hi) : "l"(v));
}
__device__ __forceinline__ u64 ffma2(u64 a, u64 b, u64 c) {
    u64 d; asm("fma.rn.f32x2 %0, %1, %2, %3;" : "=l"(d) : "l"(a), "l"(b), "l"(c)); return d;
}
__device__ __forceinline__ float ftanh(float x) {
    float y; asm("tanh.approx.f32 %0, %1;" : "=f"(y) : "f"(x)); return y;
}
__device__ __forceinline__ float fsig(float x) {
    return fmaf(0.5f, ftanh(0.5f * x), 0.5f);
}

__global__ __launch_bounds__(NTH)
void lstm_recursive_kernel(const float* __restrict__ x,
                           const float* __restrict__ W_ih,
                           const float* __restrict__ W_hh,
                           const float* __restrict__ b_ih,
                           const float* __restrict__ b_hh,
                           const float* __restrict__ W_fc,
                           const float* __restrict__ b_fc,
                           float* __restrict__ out) {
    const int j  = threadIdx.x;                    // 0..63, ALL lanes active (branchless)
    const int jr = (j < HH) ? j : (HH - 1);        // clamped row: lanes 50-63 duplicate row 49
    const int b0 = blockIdx.x * EPB;

    // h buffers padded to 64: [0..49] real, [50..63] scratch written by clamped lanes
    __shared__ __align__(16) float sh[EPB][2][64];
    __shared__ float swin[EPB][TT + NPRED];
    __shared__ float sred[EPB][64];

#pragma unroll
    for (int e = 0; e < EPB; e++)
        for (int i = j; i < TT; i += NTH) swin[e][i] = x[(b0 + e) * TT + i];

    // thread owns gate rows jr, jr+50, jr+100, jr+150 (i,f,g,o) for BOTH elements
    u64 w[4][25];                    // 200 regs of packed W_hh K-pairs (shared across elements)
    float wih[4], bsum[4];
#pragma unroll
    for (int g = 0; g < 4; g++) {
        const int row = g * HH + jr;
        const float2* wr = (const float2*)(W_hh + row * HH);   // 8B aligned
#pragma unroll
        for (int k = 0; k < 25; k++) {
            float2 v = wr[k];
            w[g][k] = pk2(v.x, v.y);
        }
        wih[g]  = W_ih[row];
        bsum[g] = b_ih[row] + b_hh[row];
    }
    const float wfc = (j < HH) ? W_fc[jr] : 0.0f;   // zero so padded sred entries are 0
    const float bfc = b_fc[0];

    // ---- phase stagger: odd blocks burn ~600 cyc so co-resident SMSP warps
    // ---- from neighboring blocks run anti-phased (FMA phase overlaps tail)
    if (blockIdx.x & 1) {
        float z = 1.0f;
#pragma unroll 1
        for (int i = 0; i < 150; i++) z = fmaf(z, 0.9999999f, 1e-30f);
        asm volatile("" :: "f"(z));                 // keep the chain alive
    }

    for (int p = 0; p < NPRED; p++) {
#pragma unroll
        for (int e = 0; e < EPB; e++) { sh[e][0][j] = 0.0f; sh[e][1][j] = 0.0f; }
        float c[EPB], hnew[EPB];
#pragma unroll
        for (int e = 0; e < EPB; e++) { c[e] = 0.0f; hnew[e] = 0.0f; }
        __syncthreads();

#pragma unroll 1
        for (int t = 0; t < TT; t++) {
            const int buf = t & 1;
            // 4 accumulator pairs per element -> 8 independent FFMA2 chains
            u64 a0[EPB], a1[EPB], a2[EPB], a3[EPB];
#pragma unroll
            for (int e = 0; e < EPB; e++) {
                const float xt = swin[e][p + t];
                a0[e] = pk2(fmaf(xt, wih[0], bsum[0]), 0.0f);
                a1[e] = pk2(fmaf(xt, wih[1], bsum[1]), 0.0f);
                a2[e] = pk2(fmaf(xt, wih[2], bsum[2]), 0.0f);
                a3[e] = pk2(fmaf(xt, wih[3], bsum[3]), 0.0f);
            }
            const ulonglong2* h0 = (const ulonglong2*)sh[0][buf];
            const ulonglong2* h1 = (const ulonglong2*)sh[1][buf];
#pragma unroll
            for (int cc = 0; cc < 12; cc++) {
                ulonglong2 hvA = h0[cc];           // LDS.128: hA[4cc..4cc+3] (broadcast)
                ulonglong2 hvB = h1[cc];
                a0[0] = ffma2(w[0][2 * cc], hvA.x, a0[0]);
                a1[0] = ffma2(w[1][2 * cc], hvA.x, a1[0]);
                a2[0] = ffma2(w[2][2 * cc], hvA.x, a2[0]);
                a3[0] = ffma2(w[3][2 * cc], hvA.x, a3[0]);
                a0[1] = ffma2(w[0][2 * cc], hvB.x, a0[1]);
                a1[1] = ffma2(w[1][2 * cc], hvB.x, a1[1]);
                a2[1] = ffma2(w[2][2 * cc], hvB.x, a2[1]);
                a3[1] = ffma2(w[3][2 * cc], hvB.x, a3[1]);
                a0[0] = ffma2(w[0][2 * cc + 1], hvA.y, a0[0]);
                a1[0] = ffma2(w[1][2 * cc + 1], hvA.y, a1[0]);
                a2[0] = ffma2(w[2][2 * cc + 1], hvA.y, a2[0]);
                a3[0] = ffma2(w[3][2 * cc + 1], hvA.y, a3[0]);
                a0[1] = ffma2(w[0][2 * cc + 1], hvB.y, a0[1]);
                a1[1] = ffma2(w[1][2 * cc + 1], hvB.y, a1[1]);
                a2[1] = ffma2(w[2][2 * cc + 1], hvB.y, a2[1]);
                a3[1] = ffma2(w[3][2 * cc + 1], hvB.y, a3[1]);
            }
            {   // k = 48, 49
                u64 htA = ((const u64*)sh[0][buf])[24];
                u64 htB = ((const u64*)sh[1][buf])[24];
                a0[0] = ffma2(w[0][24], htA, a0[0]);
                a1[0] = ffma2(w[1][24], htA, a1[0]);
                a2[0] = ffma2(w[2][24], htA, a2[0]);
                a3[0] = ffma2(w[3][24], htA, a3[0]);
                a0[1] = ffma2(w[0][24], htB, a0[1]);
                a1[1] = ffma2(w[1][24], htB, a1[1]);
                a2[1] = ffma2(w[2][24], htB, a2[1]);
                a3[1] = ffma2(w[3][24], htB, a3[1]);
            }
#pragma unroll
            for (int e = 0; e < EPB; e++) {
                float l0, hi0, l1, hi1, l2, hi2, l3, hi3;
                upk2(a0[e], l0, hi0);
                upk2(a1[e], l1, hi1);
                upk2(a2[e], l2, hi2);
                upk2(a3[e], l3, hi3);
                const float i_ = fsig(l0 + hi0);
                const float f_ = fsig(l1 + hi1);
                const float g_ = ftanh(l2 + hi2);
                const float o_ = fsig(l3 + hi3);
                c[e]    = fmaf(f_, c[e], i_ * g_);
                hnew[e] = o_ * ftanh(c[e]);
                sh[e][buf ^ 1][j] = hnew[e];       // lanes 50-63 write pad slots (harmless)
            }
            __syncthreads();                       // new h visible for next step
        }

        // FC head: out = h . W_fc + b_fc  (wfc==0 for pad lanes -> sred pad entries are 0)
#pragma unroll
        for (int e = 0; e < EPB; e++) sred[e][j] = hnew[e] * wfc;
        __syncthreads();
        if (j < EPB) {
            float s = bfc;
#pragma unroll
            for (int k = 0; k < HH; k++) s += sred[j][k];
            swin[j][TT + p] = s;
            out[(b0 + j) * NPRED + p] = s;
        }
        __syncthreads();
    }
}

extern "C" void kernel_launch(void* const* d_in, const int* in_sizes, int n_in,
                              void* d_out, int out_size) {
    const float* x    = (const float*)d_in[0];
    const float* W_ih = (const float*)d_in[1];
    const float* W_hh = (const float*)d_in[2];
    const float* b_ih = (const float*)d_in[3];
    const float* b_hh = (const float*)d_in[4];
    const float* W_fc = (const float*)d_in[5];
    const float* b_fc = (const float*)d_in[6];
    float* out = (float*)d_out;

    const int B = out_size / NPRED;               // 1024
    lstm_recursive_kernel<<<B / EPB, NTH>>>(x, W_ih, W_hh, b_ih, b_hh, W_fc, b_fc, out);
}